// round 1
// baseline (speedup 1.0000x reference)
#include <cuda_runtime.h>
#include <math.h>

// logZ of Conditional Poisson: log of K-th elementary symmetric polynomial of
// exp(weights), D = 8192, K = 256.
//
// Algorithm: product of D linear polynomials (1 + e^{w_d} x) in the log
// semiring, truncated at degree K (exact for coefficient K). Phase 1 builds
// 64 chunk polynomials (128 items each) in parallel; a 6-level binary tree of
// log-domain convolutions combines them.

#define NEGV   (-1e9f)
#define DMAX   256          // truncation degree (= K)
#define NC     257          // coefficients per polynomial (0..DMAX)
#define CHUNK  128          // items per phase-1 chunk
#define NCHUNK 64           // 8192 / 128

// Scratch (no allocations allowed): ping-pong polynomial buffers.
__device__ float g_bufA[NCHUNK * NC];
__device__ float g_bufB[NCHUNK * NC];

__device__ __forceinline__ float lae(float a, float b) {
    // logaddexp, stable: max + log1p(exp(min-max))
    float m = fmaxf(a, b);
    float d = fminf(a, b) - m;          // <= 0
    return m + log1pf(__expf(d));
}

// ---------------------------------------------------------------------------
// Phase 1: each block turns CHUNK items into a degree-CHUNK log-coef poly.
// s[j] = log ESP_j of the chunk's exp(weights). Parallel over coefficients,
// sequential over items (the only true dependency).
// ---------------------------------------------------------------------------
__global__ void phase1_kernel(const float* __restrict__ w) {
    __shared__ float s[CHUNK + 1];
    __shared__ float ws[CHUNK];
    const int tid = threadIdx.x;
    const int c   = blockIdx.x;

    for (int j = tid; j <= CHUNK; j += blockDim.x) s[j] = (j == 0) ? 0.0f : NEGV;
    for (int j = tid; j <  CHUNK; j += blockDim.x) ws[j] = w[c * CHUNK + j];
    __syncthreads();

    #pragma unroll 4
    for (int it = 0; it < CHUNK; ++it) {
        const float wv   = ws[it];
        const float left = (tid >= 1 && tid <= CHUNK) ? s[tid - 1] : NEGV;
        __syncthreads();
        if (tid >= 1 && tid <= CHUNK) s[tid] = lae(s[tid], wv + left);
        __syncthreads();
    }

    float* dst = g_bufA + c * NC;
    for (int j = tid; j < NC; j += blockDim.x)
        dst[j] = (j <= CHUNK) ? s[j] : NEGV;   // pad degrees >CHUNK with semiring zero
}

// ---------------------------------------------------------------------------
// Tree combine: log-domain convolution of adjacent polynomial pairs,
// truncated at degree DMAX. One warp per output coefficient; online
// max-rescaled exp-sum + warp shuffle reduction.
// ab=0: A->B, ab=1: B->A. On the final level, write out[0] = poly[K].
// ---------------------------------------------------------------------------
__global__ void combine_kernel(int ab, int dsrc, int is_last,
                               const int* __restrict__ Kp,
                               float* __restrict__ out) {
    const float* src = ab ? g_bufB : g_bufA;
    float*       dst = ab ? g_bufA : g_bufB;

    const int pair = blockIdx.y;
    const int warp = threadIdx.x >> 5;
    const int lane = threadIdx.x & 31;
    const int j    = blockIdx.x * (blockDim.x >> 5) + warp;
    if (j >= NC) return;                       // whole-warp uniform exit

    const float* a = src + (2 * pair)     * NC;
    const float* b = src + (2 * pair + 1) * NC;

    const int ilo = max(0, j - dsrc);
    const int ihi = min(j, dsrc);

    float m = -3.0e38f, ssum = 0.0f;
    for (int i = ilo + lane; i <= ihi; i += 32) {
        const float t  = a[i] + b[j - i];
        const float mn = fmaxf(m, t);
        ssum = ssum * __expf(m - mn) + __expf(t - mn);
        m = mn;
    }
    // warp-level (m, s) reduction
    #pragma unroll
    for (int off = 16; off; off >>= 1) {
        const float mo = __shfl_xor_sync(0xffffffffu, m,    off);
        const float so = __shfl_xor_sync(0xffffffffu, ssum, off);
        const float mn = fmaxf(m, mo);
        ssum = ssum * __expf(m - mn) + so * __expf(mo - mn);
        m = mn;
    }

    if (lane == 0) {
        const float r = (ssum > 0.0f) ? (m + logf(ssum)) : NEGV;
        dst[pair * NC + j] = r;
        if (is_last && pair == 0) {
            int K = Kp ? *Kp : DMAX;
            K = min(max(K, 0), DMAX);
            if (j == K) out[0] = r;
        }
    }
}

// ---------------------------------------------------------------------------
extern "C" void kernel_launch(void* const* d_in, const int* in_sizes, int n_in,
                              void* d_out, int out_size) {
    const float* w  = (const float*)d_in[0];
    const int*   Kp = (n_in >= 2) ? (const int*)d_in[1] : nullptr;
    float*       out = (float*)d_out;
    (void)in_sizes; (void)out_size;

    // Phase 1: 64 chunk polynomials into g_bufA.
    phase1_kernel<<<NCHUNK, 160>>>(w);

    // Tree: 64 -> 32 -> 16 -> 8 -> 4 -> 2 -> 1
    const dim3 blk(256);                       // 8 warps = 8 output coeffs/block
    const int  gx = (NC + 7) / 8;              // 33
    combine_kernel<<<dim3(gx, 32), blk>>>(0, CHUNK, 0, Kp, out);  // A->B, deg 128 src
    combine_kernel<<<dim3(gx, 16), blk>>>(1, DMAX, 0, Kp, out);   // B->A
    combine_kernel<<<dim3(gx,  8), blk>>>(0, DMAX, 0, Kp, out);   // A->B
    combine_kernel<<<dim3(gx,  4), blk>>>(1, DMAX, 0, Kp, out);   // B->A
    combine_kernel<<<dim3(gx,  2), blk>>>(0, DMAX, 0, Kp, out);   // A->B
    combine_kernel<<<dim3(gx,  1), blk>>>(1, DMAX, 1, Kp, out);   // B->A, writes out[0]
}

// round 2
// speedup vs baseline: 1.5341x; 1.5341x over previous
#include <cuda_runtime.h>
#include <math.h>

// logZ of Conditional Poisson = log ESP_K(exp(w)), D=8192, K=256.
//
// Structure:
//  K1 (32 blocks x 256 thr): each warp does a 32-item chunk DP in *linear*
//     fp32 registers (shfl_up + FMA; ESP_j of 32 items <= 4.7e22 so no
//     overflow), then the block combines its 8 chunk polys 32->64->128->256
//     via two-pass log-domain convolutions in shared memory.
//  5 upper combine launches: warp-per-output-coefficient, two-pass
//     (fmax-reduce, then independent exps + sum-reduce), ping-pong buffers.

#define NC     257
#define NBLK1  32          // 32 blocks * 8 warps * 32 items = 8192

__device__ float g_bufA[NBLK1 * NC];
__device__ float g_bufB[NBLK1 * NC];

// ---------------------------------------------------------------------------
// K1: chunk DP (linear, registers) + in-block tree to a degree-256 log-poly.
// ---------------------------------------------------------------------------
__global__ __launch_bounds__(256) void k1_kernel(const float* __restrict__ w) {
    __shared__ float sP[8 * 33];    // 8 polys, deg 32
    __shared__ float sQ[4 * 65];    // 4 polys, deg 64
    __shared__ float sR[2 * 129];   // 2 polys, deg 128

    const int tid  = threadIdx.x;
    const int lane = tid & 31;
    const int warp = tid >> 5;

    // --- 32-item chunk DP, fully in registers, linear domain ---
    // lane l holds v[l+1] = ESP_{l+1}; v[0]=1 implicit.
    float x = __expf(w[(blockIdx.x * 8 + warp) * 32 + lane]);
    float v = 0.0f;
    #pragma unroll
    for (int it = 0; it < 32; ++it) {
        const float xi   = __shfl_sync(0xffffffffu, x, it);
        float       prev = __shfl_up_sync(0xffffffffu, v, 1);
        if (lane == 0) prev = 1.0f;
        v = fmaf(xi, prev, v);
    }
    if (lane == 0) sP[warp * 33] = 0.0f;       // log ESP_0 = 0
    sP[warp * 33 + lane + 1] = __logf(v);
    __syncthreads();

    // --- level 1: 4 convs, deg 32 + 32 -> 64 ---
    for (int idx = tid; idx < 4 * 65; idx += 256) {
        const int c = idx / 65, j = idx % 65;
        const float* a = sP + (2 * c)     * 33;
        const float* b = sP + (2 * c + 1) * 33;
        const int lo = j > 32 ? j - 32 : 0;
        const int hi = j < 32 ? j : 32;
        float m = -1e30f;
        #pragma unroll 4
        for (int i = lo; i <= hi; ++i) m = fmaxf(m, a[i] + b[j - i]);
        float s = 0.0f;
        #pragma unroll 4
        for (int i = lo; i <= hi; ++i) s += __expf(a[i] + b[j - i] - m);
        sQ[c * 65 + j] = m + __logf(s);
    }
    __syncthreads();

    // --- level 2: 2 convs, deg 64 + 64 -> 128 ---
    for (int idx = tid; idx < 2 * 129; idx += 256) {
        const int c = idx / 129, j = idx % 129;
        const float* a = sQ + (2 * c)     * 65;
        const float* b = sQ + (2 * c + 1) * 65;
        const int lo = j > 64 ? j - 64 : 0;
        const int hi = j < 64 ? j : 64;
        float m = -1e30f;
        #pragma unroll 4
        for (int i = lo; i <= hi; ++i) m = fmaxf(m, a[i] + b[j - i]);
        float s = 0.0f;
        #pragma unroll 4
        for (int i = lo; i <= hi; ++i) s += __expf(a[i] + b[j - i] - m);
        sR[c * 129 + j] = m + __logf(s);
    }
    __syncthreads();

    // --- level 3: 1 conv, deg 128 + 128 -> 256, write to global ---
    for (int j = tid; j < NC; j += 256) {
        const float* a = sR;
        const float* b = sR + 129;
        const int lo = j > 128 ? j - 128 : 0;
        const int hi = j < 128 ? j : 128;
        float m = -1e30f;
        #pragma unroll 4
        for (int i = lo; i <= hi; ++i) m = fmaxf(m, a[i] + b[j - i]);
        float s = 0.0f;
        #pragma unroll 4
        for (int i = lo; i <= hi; ++i) s += __expf(a[i] + b[j - i] - m);
        g_bufA[blockIdx.x * NC + j] = m + __logf(s);
    }
}

// ---------------------------------------------------------------------------
// Upper tree: warp-per-output-coefficient, two-pass logsumexp convolution.
// Polys all have full degree 256 (every coefficient finite), so i in [0..j].
// ---------------------------------------------------------------------------
__global__ __launch_bounds__(256) void combine_up(int ab, int is_last,
                                                  const int* __restrict__ Kp,
                                                  float* __restrict__ out) {
    const float* src = ab ? g_bufB : g_bufA;
    float*       dst = ab ? g_bufA : g_bufB;

    const int pair = blockIdx.y;
    const int lane = threadIdx.x & 31;
    const int j    = blockIdx.x * 8 + (threadIdx.x >> 5);
    if (j >= NC) return;                        // uniform per warp

    const float* a = src + (2 * pair) * NC;
    const float* b = a + NC;

    // pass 1: max
    float m = -1e30f;
    for (int i = lane; i <= j; i += 32) m = fmaxf(m, a[i] + b[j - i]);
    #pragma unroll
    for (int o = 16; o; o >>= 1) m = fmaxf(m, __shfl_xor_sync(0xffffffffu, m, o));

    // pass 2: sum of exps (independent MUFU ops, no serial rescale chain)
    float s = 0.0f;
    for (int i = lane; i <= j; i += 32) s += __expf(a[i] + b[j - i] - m);
    #pragma unroll
    for (int o = 16; o; o >>= 1) s += __shfl_xor_sync(0xffffffffu, s, o);

    if (lane == 0) {
        const float r = m + __logf(s);
        dst[pair * NC + j] = r;
        if (is_last && pair == 0) {
            int K = Kp ? *Kp : 256;
            K = min(max(K, 0), 256);
            if (j == K) out[0] = r;
        }
    }
}

// ---------------------------------------------------------------------------
extern "C" void kernel_launch(void* const* d_in, const int* in_sizes, int n_in,
                              void* d_out, int out_size) {
    const float* w   = (const float*)d_in[0];
    const int*   Kp  = (n_in >= 2) ? (const int*)d_in[1] : nullptr;
    float*       out = (float*)d_out;
    (void)in_sizes; (void)out_size;

    k1_kernel<<<NBLK1, 256>>>(w);               // 32 deg-256 polys -> bufA

    const dim3 blk(256);
    const int  gx = (NC + 7) / 8;               // 33
    combine_up<<<dim3(gx, 16), blk>>>(0, 0, Kp, out);  // 32 -> 16  (A->B)
    combine_up<<<dim3(gx,  8), blk>>>(1, 0, Kp, out);  // 16 -> 8   (B->A)
    combine_up<<<dim3(gx,  4), blk>>>(0, 0, Kp, out);  // 8  -> 4   (A->B)
    combine_up<<<dim3(gx,  2), blk>>>(1, 0, Kp, out);  // 4  -> 2   (B->A)
    combine_up<<<dim3(gx,  1), blk>>>(0, 1, Kp, out);  // 2  -> 1, writes out
}